// round 13
// baseline (speedup 1.0000x reference)
#include <cuda_runtime.h>
#include <math.h>

#define NEPS 1e-8f
#define MEPS 1e-6f
#define BTOL 1e-6f
#define MAXV 16
#define RED_MAX 4096
#define TPB 256

__device__ float g_partials[RED_MAX];
__device__ int   g_count = 0;

// Corner order matches reference: x4=[.5,-.5,-.5,.5]*w, y4=[-.5,-.5,.5,.5]*h
__device__ __forceinline__ void box_corners(float cx, float cy, float w, float h,
                                            float c, float s,
                                            float* X, float* Y) {
    float hw = 0.5f * w, hh = 0.5f * h;
    float xs0 =  hw, xs1 = -hw, xs2 = -hw, xs3 =  hw;
    float ys0 = -hh, ys1 = -hh, ys2 =  hh, ys3 =  hh;
    X[0] = xs0 * c - ys0 * s + cx;  Y[0] = xs0 * s + ys0 * c + cy;
    X[1] = xs1 * c - ys1 * s + cx;  Y[1] = xs1 * s + ys1 * c + cy;
    X[2] = xs2 * c - ys2 * s + cx;  Y[2] = xs2 * s + ys2 * c + cy;
    X[3] = xs3 * c - ys3 * s + cx;  Y[3] = xs3 * s + ys3 * c + cy;
}

// Monotone pseudo-angle, order-isomorphic to atan2(y,x) on (-pi, pi].
__device__ __forceinline__ float pseudo_angle(float x, float y) {
    float t = __fdividef(y, fabsf(x) + fabsf(y));
    if (x >= 0.0f) return t;
    return (y >= 0.0f) ? (2.0f - t) : (-2.0f - t);
}

// Order-preserving float -> uint32
__device__ __forceinline__ unsigned int ordered_bits(float f) {
    unsigned int u = __float_as_uint(f);
    return ((int)u < 0) ? ~u : (u | 0x80000000u);
}

// atan for x > 0; A&S 4.4.49 minimax, |err| < 1e-5
__device__ __forceinline__ float fast_atan_pos(float x) {
    bool big = (x > 1.0f);
    float r = big ? __fdividef(1.0f, x) : x;
    float r2 = r * r;
    float p = fmaf(r2, fmaf(r2, fmaf(r2, fmaf(r2, 0.0208351f, -0.0851330f),
                                     0.1801410f), -0.3302995f), 0.9998660f);
    p = r * p;
    return big ? (1.5707963267948966f - p) : p;
}

// Compare-exchange for the sorting network (branch-free, keys distinct)
#define CE(a, b) { unsigned int lo_ = min(key[a], key[b]); \
                   unsigned int hi_ = max(key[a], key[b]); \
                   key[a] = lo_; key[b] = hi_; }

__global__ __launch_bounds__(TPB, 4)
void obb_ciou_kernel(const float* __restrict__ pred,
                     const float* __restrict__ target,
                     const float* __restrict__ weight,
                     float* __restrict__ out,
                     int N, float invN) {
    __shared__ float2 s_v[MAXV][TPB];   // 32KB; row stride 2048B -> lane-invariant banks
    __shared__ float  s_p[TPB * 5];     // 5KB staged pred chunk
    __shared__ float  s_t[TPB * 5];     // 5KB staged target chunk
    const int tid = threadIdx.x;
    float2* const col = &s_v[0][tid];   // row k at col[k*TPB]

    float loss = 0.0f;
    for (int base = blockIdx.x * TPB; base < N; base += gridDim.x * TPB) {
        int cnt = min(TPB, N - base);
        __syncthreads();                 // protect staging buffers across iterations
        for (int j = tid; j < cnt * 5; j += TPB) {
            s_p[j] = pred[(size_t)base * 5 + j];
            s_t[j] = target[(size_t)base * 5 + j];
        }
        __syncthreads();

        int i = base + tid;
        if (i >= N) continue;            // (reconverges at loop head sync)

        const float* P = &s_p[tid * 5];
        const float* T = &s_t[tid * 5];
        float p_cx = P[0], p_cy = P[1], p_w = P[2], p_h = P[3], p_a = P[4];
        float t_cx = T[0], t_cy = T[1], t_w = T[2], t_h = T[3], t_a = T[4];

        float c1, s1, c2, s2;
        __sincosf(p_a, &s1, &c1);
        __sincosf(t_a, &s2, &c2);

        // ---- box1-local frame: box1 axis-aligned, box2 rotated by delta ----
        float hw = 0.5f * p_w, hh = 0.5f * p_h;
        float dxg = t_cx - p_cx, dyg = t_cy - p_cy;
        float rcx =  c1 * dxg + s1 * dyg;          // R1^T * (c2 - c1)
        float rcy =  c1 * dyg - s1 * dxg;
        float cd = c1 * c2 + s1 * s2;              // cos(a2 - a1)
        float sd = c1 * s2 - s1 * c2;              // sin(a2 - a1)

        float X2[4], Y2[4];
        box_corners(rcx, rcy, t_w, t_h, cd, sd, X2, Y2);

        // box1 corners (CW, reference order) in local frame
        const float X1a[4] = { hw, -hw, -hw,  hw };
        const float Y1a[4] = {-hh, -hh,  hh,  hh };
        const float exs[4] = {-p_w, 0.0f, p_w,  0.0f};
        const float eys[4] = { 0.0f, p_h, 0.0f, -p_h};

        // inclusion bounds (== reference p_ab/p_ad in (-tol, 1+tol))
        float bx1 = hw + BTOL * p_w, by1 = hh + BTOL * p_h;
        float bx2 = 0.5f * t_w + BTOL * t_w, by2 = 0.5f * t_h + BTOL * t_h;

        // ---- collect valid vertices (reference concatenation order) ----
        int m = 0;
        float sx = 0.0f, sy = 0.0f;

        // corners1 in box2: rotate into box2 frame, bound check
        #pragma unroll
        for (int k = 0; k < 4; k++) {
            float ux = X1a[k] - rcx, uy = Y1a[k] - rcy;
            float qx = cd * ux + sd * uy;
            float qy = cd * uy - sd * ux;
            if (fabsf(qx) < bx2 && fabsf(qy) < by2) {
                col[m * TPB] = make_float2(X1a[k], Y1a[k]);
                sx += X1a[k]; sy += Y1a[k]; m++;
            }
        }
        // corners2 in box1: direct bound check (box1 axis-aligned)
        #pragma unroll
        for (int k = 0; k < 4; k++) {
            if (fabsf(X2[k]) < bx1 && fabsf(Y2[k]) < by1) {
                col[m * TPB] = make_float2(X2[k], Y2[k]);
                sx += X2[k]; sy += Y2[k]; m++;
            }
        }
        // segment intersections, k1-major (matches reshape order)
        #pragma unroll
        for (int k1 = 0; k1 < 4; k1++) {
            float x1 = X1a[k1], y1 = Y1a[k1];
            float ex = exs[k1],  ey = eys[k1];   // literal zeros fold
            #pragma unroll
            for (int k2 = 0; k2 < 4; k2++) {
                float x3 = X2[k2], y3 = Y2[k2];
                float fx = X2[(k2 + 1) & 3] - x3, fy = Y2[(k2 + 1) & 3] - y3;
                float ax = x1 - x3, ay = y1 - y3;
                float num   = ex * fy - ey * fx;
                float den_t = fx * ay - fy * ax;
                float den_u = ex * ay - ey * ax;
                float inum  = __fdividef(1.0f, num + NEPS);
                float t = den_t * inum;
                float u = -den_u * inum;
                bool ok = (num != 0.0f) &&
                          (t > 0.0f) && (t < 1.0f) &&
                          (u > 0.0f) && (u < 1.0f);
                if (ok) {
                    float ix = fmaf(t, ex, x1);
                    float iy = fmaf(t, ey, y1);
                    col[m * TPB] = make_float2(ix, iy);
                    sx += ix; sy += iy; m++;
                }
            }
        }

        // ---- order by centroid angle, shoelace (area frame-invariant) ----
        float inter_area = 0.0f;
        if (m > 2 && m <= 8) {
            float imf = __fdividef(1.0f, (float)m);
            float ccx = sx * imf, ccy = sy * imf;

            unsigned int key[8];
            #pragma unroll
            for (int slot = 0; slot < 8; slot++) {
                unsigned int kk = 0xFFFFFFFFu;   // sentinel sorts last
                if (slot < m) {
                    float2 v = col[slot * TPB];
                    unsigned int u = ordered_bits(pseudo_angle(v.x - ccx, v.y - ccy));
                    kk = (u & 0xFFFFFFE0u) | (unsigned int)slot;
                }
                key[slot] = kk;
            }
            // Batcher odd-even merge sort, 8 elements, 19 comparators
            CE(0,1) CE(2,3) CE(4,5) CE(6,7)
            CE(0,2) CE(1,3) CE(4,6) CE(5,7)
            CE(1,2) CE(5,6)
            CE(0,4) CE(1,5) CE(2,6) CE(3,7)
            CE(2,4) CE(3,5)
            CE(1,2) CE(3,4) CE(5,6)

            float2 f0 = col[(int)(key[0] & 0x1Fu) * TPB];
            float px = f0.x, py = f0.y;
            float s = 0.0f;
            #pragma unroll
            for (int r = 1; r < 8; r++) {
                if (r < m) {
                    float2 v = col[(int)(key[r] & 0x1Fu) * TPB];
                    s = fmaf(px, v.y, s);
                    s = fmaf(-py, v.x, s);
                    px = v.x; py = v.y;
                }
            }
            s = fmaf(px, f0.y, s);
            s = fmaf(-py, f0.x, s);
            inter_area = fabsf(s) * 0.5f;
        } else if (m > 8) {
            // rare fallback (tolerance-degenerate)
            float imf = __fdividef(1.0f, (float)m);
            float ccx = sx * imf, ccy = sy * imf;

            unsigned int key[MAXV];
            for (int k = 0; k < m; k++) {
                float2 v = col[k * TPB];
                unsigned int u = ordered_bits(pseudo_angle(v.x - ccx, v.y - ccy));
                key[k] = (u & 0xFFFFFFE0u) | (unsigned int)k;
            }
            for (int k = 1; k < m; k++) {
                unsigned int kv = key[k];
                int j = k - 1;
                while (j >= 0 && key[j] > kv) { key[j + 1] = key[j]; j--; }
                key[j + 1] = kv;
            }
            float2 f0 = col[(int)(key[0] & 0x1Fu) * TPB];
            float px = f0.x, py = f0.y;
            float s = 0.0f;
            for (int k = 1; k < m; k++) {
                float2 v = col[(int)(key[k] & 0x1Fu) * TPB];
                s = fmaf(px, v.y, s);
                s = fmaf(-py, v.x, s);
                px = v.x; py = v.y;
            }
            s = fmaf(px, f0.y, s);
            s = fmaf(-py, f0.x, s);
            inter_area = fabsf(s) * 0.5f;
        }

        float area1 = p_w * p_h;
        float area2 = t_w * t_h;
        float iou = __fdividef(inter_area, area1 + area2 - inter_area);
        iou = fminf(fmaxf(iou, 0.0f), 1.0f);

        // horizontal enclosing box (global frame)
        float ac1 = fabsf(c1), as1 = fabsf(s1);
        float ac2 = fabsf(c2), as2 = fabsf(s2);
        float dw1 = (p_w * ac1 + p_h * as1) * 0.5f;
        float dh1 = (p_w * as1 + p_h * ac1) * 0.5f;
        float dw2 = (t_w * ac2 + t_h * as2) * 0.5f;
        float dh2 = (t_w * as2 + t_h * ac2) * 0.5f;
        float en_w = fmaxf(fmaxf(p_cx + dw1, t_cx + dw2) - fminf(p_cx - dw1, t_cx - dw2), 0.0f);
        float en_h = fmaxf(fmaxf(p_cy + dh1, t_cy + dh2) - fminf(p_cy - dh1, t_cy - dh2), 0.0f);
        float c2v = en_w * en_w + en_h * en_h + MEPS;

        float rho2 = dxg * dxg + dyg * dyg;

        const float factor = 0.40528473456935108577f;  // 4/pi^2
        float dv = fast_atan_pos(__fdividef(t_w, t_h + MEPS)) -
                   fast_atan_pos(__fdividef(p_w, p_h + MEPS));
        float v = factor * dv * dv;
        float alpha = (iou > 0.5f) ? __fdividef(v, 1.0f - iou + v + MEPS) : 0.0f;

        float ciou = iou - (fminf(fmaxf(__fdividef(rho2, c2v), 0.0f), 1.0f) + alpha * v);
        loss += (1.0f - ciou) * weight[i];
    }

    // ---- deterministic fixed-order reduction ----
    #pragma unroll
    for (int o = 16; o > 0; o >>= 1)
        loss += __shfl_down_sync(0xffffffffu, loss, o);
    __shared__ float sm[TPB / 32];
    __shared__ bool isLast;
    if ((tid & 31) == 0) sm[tid >> 5] = loss;
    __syncthreads();
    if (tid < 32) {
        float vsum = (tid < TPB / 32) ? sm[tid] : 0.0f;
        #pragma unroll
        for (int o = TPB / 64; o > 0; o >>= 1)
            vsum += __shfl_down_sync(0xffffffffu, vsum, o);
        if (tid == 0) {
            g_partials[blockIdx.x] = vsum;
            __threadfence();
            int prev = atomicAdd(&g_count, 1);
            isLast = (prev == (int)gridDim.x - 1);
        }
    }
    __syncthreads();
    if (isLast) {
        int nb = gridDim.x;
        float s = 0.0f;
        for (int k = tid; k < nb; k += TPB) s += g_partials[k];
        #pragma unroll
        for (int o = 16; o > 0; o >>= 1)
            s += __shfl_down_sync(0xffffffffu, s, o);
        if ((tid & 31) == 0) sm[tid >> 5] = s;
        __syncthreads();
        if (tid < 32) {
            float vs = (tid < TPB / 32) ? sm[tid] : 0.0f;
            #pragma unroll
            for (int o = TPB / 64; o > 0; o >>= 1)
                vs += __shfl_down_sync(0xffffffffu, vs, o);
            if (tid == 0) {
                out[0] = vs * invN;
                g_count = 0;   // reset for next graph replay
            }
        }
    }
}

extern "C" void kernel_launch(void* const* d_in, const int* in_sizes, int n_in,
                              void* d_out, int out_size) {
    const float* pred   = (const float*)d_in[0];
    const float* target = (const float*)d_in[1];
    const float* weight = (const float*)d_in[2];
    int N = in_sizes[2];  // weight has N elements

    int nb = (N + TPB - 1) / TPB;
    if (nb > RED_MAX) nb = RED_MAX;
    if (nb < 1) nb = 1;

    obb_ciou_kernel<<<nb, TPB>>>(pred, target, weight, (float*)d_out,
                                 N, 1.0f / (float)N);
}

// round 14
// speedup vs baseline: 1.0485x; 1.0485x over previous
#include <cuda_runtime.h>
#include <math.h>

#define NEPS 1e-8f
#define MEPS 1e-6f
#define BTOL 1e-6f
#define MAXV 16
#define RED_MAX 4096
#define TPB 256

__device__ float g_partials[RED_MAX];
__device__ int   g_count = 0;

// Corner order matches reference: x4=[.5,-.5,-.5,.5]*w, y4=[-.5,-.5,.5,.5]*h
__device__ __forceinline__ void box_corners(float cx, float cy, float w, float h,
                                            float c, float s,
                                            float* X, float* Y) {
    float hw = 0.5f * w, hh = 0.5f * h;
    float xs0 =  hw, xs1 = -hw, xs2 = -hw, xs3 =  hw;
    float ys0 = -hh, ys1 = -hh, ys2 =  hh, ys3 =  hh;
    X[0] = xs0 * c - ys0 * s + cx;  Y[0] = xs0 * s + ys0 * c + cy;
    X[1] = xs1 * c - ys1 * s + cx;  Y[1] = xs1 * s + ys1 * c + cy;
    X[2] = xs2 * c - ys2 * s + cx;  Y[2] = xs2 * s + ys2 * c + cy;
    X[3] = xs3 * c - ys3 * s + cx;  Y[3] = xs3 * s + ys3 * c + cy;
}

// Monotone pseudo-angle, order-isomorphic to atan2(y,x) on (-pi, pi].
__device__ __forceinline__ float pseudo_angle(float x, float y) {
    float t = __fdividef(y, fabsf(x) + fabsf(y));
    if (x >= 0.0f) return t;
    return (y >= 0.0f) ? (2.0f - t) : (-2.0f - t);
}

// Order-preserving float -> uint32
__device__ __forceinline__ unsigned int ordered_bits(float f) {
    unsigned int u = __float_as_uint(f);
    return ((int)u < 0) ? ~u : (u | 0x80000000u);
}

// atan for x > 0; A&S 4.4.49 minimax, |err| < 1e-5
__device__ __forceinline__ float fast_atan_pos(float x) {
    bool big = (x > 1.0f);
    float r = big ? __fdividef(1.0f, x) : x;
    float r2 = r * r;
    float p = fmaf(r2, fmaf(r2, fmaf(r2, fmaf(r2, 0.0208351f, -0.0851330f),
                                     0.1801410f), -0.3302995f), 0.9998660f);
    p = r * p;
    return big ? (1.5707963267948966f - p) : p;
}

// Compare-exchange for the sorting network (branch-free, keys distinct)
#define CE(a, b) { unsigned int lo_ = min(key[a], key[b]); \
                   unsigned int hi_ = max(key[a], key[b]); \
                   key[a] = lo_; key[b] = hi_; }

__global__ __launch_bounds__(TPB, 4)
void obb_ciou_kernel(const float* __restrict__ pred,
                     const float* __restrict__ target,
                     const float* __restrict__ weight,
                     float* __restrict__ out,
                     int N, float invN) {
    __shared__ float2 s_v[MAXV][TPB];   // 32KB; row stride 2048B -> lane-invariant banks
    const int tid = threadIdx.x;
    float2* const col = &s_v[0][tid];   // row k at col[k*TPB]

    float loss = 0.0f;
    for (int i = blockIdx.x * TPB + tid; i < N; i += gridDim.x * TPB) {
        const float* P = pred + (size_t)i * 5;
        const float* T = target + (size_t)i * 5;
        float p_cx = P[0], p_cy = P[1], p_w = P[2], p_h = P[3], p_a = P[4];
        float t_cx = T[0], t_cy = T[1], t_w = T[2], t_h = T[3], t_a = T[4];

        float c1, s1, c2, s2;
        __sincosf(p_a, &s1, &c1);
        __sincosf(t_a, &s2, &c2);

        // ---- box1-local frame: box1 axis-aligned, box2 rotated by delta ----
        float hw = 0.5f * p_w, hh = 0.5f * p_h;
        float dxg = t_cx - p_cx, dyg = t_cy - p_cy;
        float rcx =  c1 * dxg + s1 * dyg;          // R1^T * (c2 - c1)
        float rcy =  c1 * dyg - s1 * dxg;
        float cd = c1 * c2 + s1 * s2;              // cos(a2 - a1)
        float sd = c1 * s2 - s1 * c2;              // sin(a2 - a1)

        float X2[4], Y2[4];
        box_corners(rcx, rcy, t_w, t_h, cd, sd, X2, Y2);

        // box1 corners (CW, reference order) in local frame
        const float X1a[4] = { hw, -hw, -hw,  hw };
        const float Y1a[4] = {-hh, -hh,  hh,  hh };
        const float exs[4] = {-p_w, 0.0f, p_w,  0.0f};
        const float eys[4] = { 0.0f, p_h, 0.0f, -p_h};

        // inclusion bounds (== reference p_ab/p_ad in (-tol, 1+tol))
        float bx1 = hw + BTOL * p_w, by1 = hh + BTOL * p_h;
        float bx2 = 0.5f * t_w + BTOL * t_w, by2 = 0.5f * t_h + BTOL * t_h;

        // ---- collect valid vertices (reference concatenation order) ----
        int m = 0;
        float sx = 0.0f, sy = 0.0f;

        // corners1 in box2: rotate into box2 frame, bound check
        #pragma unroll
        for (int k = 0; k < 4; k++) {
            float ux = X1a[k] - rcx, uy = Y1a[k] - rcy;
            float qx = cd * ux + sd * uy;
            float qy = cd * uy - sd * ux;
            if (fabsf(qx) < bx2 && fabsf(qy) < by2) {
                col[m * TPB] = make_float2(X1a[k], Y1a[k]);
                sx += X1a[k]; sy += Y1a[k]; m++;
            }
        }
        // corners2 in box1: direct bound check (box1 axis-aligned)
        #pragma unroll
        for (int k = 0; k < 4; k++) {
            if (fabsf(X2[k]) < bx1 && fabsf(Y2[k]) < by1) {
                col[m * TPB] = make_float2(X2[k], Y2[k]);
                sx += X2[k]; sy += Y2[k]; m++;
            }
        }
        // segment intersections, k1-major (matches reshape order)
        // Division-free accept test; exact reference t only on accept.
        #pragma unroll
        for (int k1 = 0; k1 < 4; k1++) {
            float x1 = X1a[k1], y1 = Y1a[k1];
            float ex = exs[k1],  ey = eys[k1];   // literal zeros fold
            #pragma unroll
            for (int k2 = 0; k2 < 4; k2++) {
                float x3 = X2[k2], y3 = Y2[k2];
                float fx = X2[(k2 + 1) & 3] - x3, fy = Y2[(k2 + 1) & 3] - y3;
                float ax = x1 - x3, ay = y1 - y3;
                float num   = ex * fy - ey * fx;
                float den_t = fx * ay - fy * ax;
                float den_u = ex * ay - ey * ax;
                // t = den_t/(num+e) in (0,1)  <=>  den_t*num>0 && |den_t|<|num|
                // u = -den_u/(num+e) in (0,1) <=>  den_u*num<0 && |den_u|<|num|
                bool ok = (den_t * num > 0.0f) && (fabsf(den_t) < fabsf(num)) &&
                          (den_u * num < 0.0f) && (fabsf(den_u) < fabsf(num));
                if (ok) {
                    float t = __fdividef(den_t, num + NEPS);
                    float ix = fmaf(t, ex, x1);
                    float iy = fmaf(t, ey, y1);
                    col[m * TPB] = make_float2(ix, iy);
                    sx += ix; sy += iy; m++;
                }
            }
        }

        // ---- order by centroid angle, shoelace (area frame-invariant) ----
        float inter_area = 0.0f;
        if (m > 2 && m <= 8) {
            float imf = __fdividef(1.0f, (float)m);
            float ccx = sx * imf, ccy = sy * imf;

            unsigned int key[8];
            #pragma unroll
            for (int slot = 0; slot < 8; slot++) {
                unsigned int kk = 0xFFFFFFFFu;   // sentinel sorts last
                if (slot < m) {
                    float2 v = col[slot * TPB];
                    unsigned int u = ordered_bits(pseudo_angle(v.x - ccx, v.y - ccy));
                    kk = (u & 0xFFFFFFE0u) | (unsigned int)slot;
                }
                key[slot] = kk;
            }
            // Batcher odd-even merge sort, 8 elements, 19 comparators
            CE(0,1) CE(2,3) CE(4,5) CE(6,7)
            CE(0,2) CE(1,3) CE(4,6) CE(5,7)
            CE(1,2) CE(5,6)
            CE(0,4) CE(1,5) CE(2,6) CE(3,7)
            CE(2,4) CE(3,5)
            CE(1,2) CE(3,4) CE(5,6)

            float2 f0 = col[(int)(key[0] & 0x1Fu) * TPB];
            float px = f0.x, py = f0.y;
            float s = 0.0f;
            #pragma unroll
            for (int r = 1; r < 8; r++) {
                if (r < m) {
                    float2 v = col[(int)(key[r] & 0x1Fu) * TPB];
                    s = fmaf(px, v.y, s);
                    s = fmaf(-py, v.x, s);
                    px = v.x; py = v.y;
                }
            }
            s = fmaf(px, f0.y, s);
            s = fmaf(-py, f0.x, s);
            inter_area = fabsf(s) * 0.5f;
        } else if (m > 8) {
            // rare fallback (tolerance-degenerate)
            float imf = __fdividef(1.0f, (float)m);
            float ccx = sx * imf, ccy = sy * imf;

            unsigned int key[MAXV];
            for (int k = 0; k < m; k++) {
                float2 v = col[k * TPB];
                unsigned int u = ordered_bits(pseudo_angle(v.x - ccx, v.y - ccy));
                key[k] = (u & 0xFFFFFFE0u) | (unsigned int)k;
            }
            for (int k = 1; k < m; k++) {
                unsigned int kv = key[k];
                int j = k - 1;
                while (j >= 0 && key[j] > kv) { key[j + 1] = key[j]; j--; }
                key[j + 1] = kv;
            }
            float2 f0 = col[(int)(key[0] & 0x1Fu) * TPB];
            float px = f0.x, py = f0.y;
            float s = 0.0f;
            for (int k = 1; k < m; k++) {
                float2 v = col[(int)(key[k] & 0x1Fu) * TPB];
                s = fmaf(px, v.y, s);
                s = fmaf(-py, v.x, s);
                px = v.x; py = v.y;
            }
            s = fmaf(px, f0.y, s);
            s = fmaf(-py, f0.x, s);
            inter_area = fabsf(s) * 0.5f;
        }

        float area1 = p_w * p_h;
        float area2 = t_w * t_h;
        float iou = __fdividef(inter_area, area1 + area2 - inter_area);
        iou = fminf(fmaxf(iou, 0.0f), 1.0f);

        // horizontal enclosing box (global frame)
        float ac1 = fabsf(c1), as1 = fabsf(s1);
        float ac2 = fabsf(c2), as2 = fabsf(s2);
        float dw1 = (p_w * ac1 + p_h * as1) * 0.5f;
        float dh1 = (p_w * as1 + p_h * ac1) * 0.5f;
        float dw2 = (t_w * ac2 + t_h * as2) * 0.5f;
        float dh2 = (t_w * as2 + t_h * ac2) * 0.5f;
        float en_w = fmaxf(fmaxf(p_cx + dw1, t_cx + dw2) - fminf(p_cx - dw1, t_cx - dw2), 0.0f);
        float en_h = fmaxf(fmaxf(p_cy + dh1, t_cy + dh2) - fminf(p_cy - dh1, t_cy - dh2), 0.0f);
        float c2v = en_w * en_w + en_h * en_h + MEPS;

        float rho2 = dxg * dxg + dyg * dyg;

        const float factor = 0.40528473456935108577f;  // 4/pi^2
        float dv = fast_atan_pos(__fdividef(t_w, t_h + MEPS)) -
                   fast_atan_pos(__fdividef(p_w, p_h + MEPS));
        float v = factor * dv * dv;
        float alpha = (iou > 0.5f) ? __fdividef(v, 1.0f - iou + v + MEPS) : 0.0f;

        float ciou = iou - (fminf(fmaxf(__fdividef(rho2, c2v), 0.0f), 1.0f) + alpha * v);
        loss += (1.0f - ciou) * weight[i];
    }

    // ---- deterministic fixed-order reduction ----
    #pragma unroll
    for (int o = 16; o > 0; o >>= 1)
        loss += __shfl_down_sync(0xffffffffu, loss, o);
    __shared__ float sm[TPB / 32];
    __shared__ bool isLast;
    if ((tid & 31) == 0) sm[tid >> 5] = loss;
    __syncthreads();
    if (tid < 32) {
        float vsum = (tid < TPB / 32) ? sm[tid] : 0.0f;
        #pragma unroll
        for (int o = TPB / 64; o > 0; o >>= 1)
            vsum += __shfl_down_sync(0xffffffffu, vsum, o);
        if (tid == 0) {
            g_partials[blockIdx.x] = vsum;
            __threadfence();
            int prev = atomicAdd(&g_count, 1);
            isLast = (prev == (int)gridDim.x - 1);
        }
    }
    __syncthreads();
    if (isLast) {
        int nb = gridDim.x;
        float s = 0.0f;
        for (int k = tid; k < nb; k += TPB) s += g_partials[k];
        #pragma unroll
        for (int o = 16; o > 0; o >>= 1)
            s += __shfl_down_sync(0xffffffffu, s, o);
        if ((tid & 31) == 0) sm[tid >> 5] = s;
        __syncthreads();
        if (tid < 32) {
            float vs = (tid < TPB / 32) ? sm[tid] : 0.0f;
            #pragma unroll
            for (int o = TPB / 64; o > 0; o >>= 1)
                vs += __shfl_down_sync(0xffffffffu, vs, o);
            if (tid == 0) {
                out[0] = vs * invN;
                g_count = 0;   // reset for next graph replay
            }
        }
    }
}

extern "C" void kernel_launch(void* const* d_in, const int* in_sizes, int n_in,
                              void* d_out, int out_size) {
    const float* pred   = (const float*)d_in[0];
    const float* target = (const float*)d_in[1];
    const float* weight = (const float*)d_in[2];
    int N = in_sizes[2];  // weight has N elements

    int nb = (N + TPB - 1) / TPB;
    if (nb > RED_MAX) nb = RED_MAX;
    if (nb < 1) nb = 1;

    obb_ciou_kernel<<<nb, TPB>>>(pred, target, weight, (float*)d_out,
                                 N, 1.0f / (float)N);
}

// round 15
// speedup vs baseline: 1.1105x; 1.0591x over previous
#include <cuda_runtime.h>
#include <math.h>

#define NEPS 1e-8f
#define MEPS 1e-6f
#define BTOL 1e-6f
#define MAXV 16
#define RED_MAX 4096
#define TPB 256

__device__ float g_partials[RED_MAX];
__device__ int   g_count = 0;

// Corner order matches reference: x4=[.5,-.5,-.5,.5]*w, y4=[-.5,-.5,.5,.5]*h
__device__ __forceinline__ void box_corners(float cx, float cy, float w, float h,
                                            float c, float s,
                                            float* X, float* Y) {
    float hw = 0.5f * w, hh = 0.5f * h;
    float xs0 =  hw, xs1 = -hw, xs2 = -hw, xs3 =  hw;
    float ys0 = -hh, ys1 = -hh, ys2 =  hh, ys3 =  hh;
    X[0] = xs0 * c - ys0 * s + cx;  Y[0] = xs0 * s + ys0 * c + cy;
    X[1] = xs1 * c - ys1 * s + cx;  Y[1] = xs1 * s + ys1 * c + cy;
    X[2] = xs2 * c - ys2 * s + cx;  Y[2] = xs2 * s + ys2 * c + cy;
    X[3] = xs3 * c - ys3 * s + cx;  Y[3] = xs3 * s + ys3 * c + cy;
}

// Monotone pseudo-angle, order-isomorphic to atan2(y,x) on (-pi, pi].
__device__ __forceinline__ float pseudo_angle(float x, float y) {
    float t = __fdividef(y, fabsf(x) + fabsf(y));
    if (x >= 0.0f) return t;
    return (y >= 0.0f) ? (2.0f - t) : (-2.0f - t);
}

// Order-preserving float -> uint32
__device__ __forceinline__ unsigned int ordered_bits(float f) {
    unsigned int u = __float_as_uint(f);
    return ((int)u < 0) ? ~u : (u | 0x80000000u);
}

// atan for x > 0; A&S 4.4.49 minimax, |err| < 1e-5
__device__ __forceinline__ float fast_atan_pos(float x) {
    bool big = (x > 1.0f);
    float r = big ? __fdividef(1.0f, x) : x;
    float r2 = r * r;
    float p = fmaf(r2, fmaf(r2, fmaf(r2, fmaf(r2, 0.0208351f, -0.0851330f),
                                     0.1801410f), -0.3302995f), 0.9998660f);
    p = r * p;
    return big ? (1.5707963267948966f - p) : p;
}

// Compare-exchange for the sorting network (branch-free, keys distinct)
#define CE(a, b) { unsigned int lo_ = min(key[a], key[b]); \
                   unsigned int hi_ = max(key[a], key[b]); \
                   key[a] = lo_; key[b] = hi_; }

__global__ __launch_bounds__(TPB, 4)
void obb_ciou_kernel(const float* __restrict__ pred,
                     const float* __restrict__ target,
                     const float* __restrict__ weight,
                     float* __restrict__ out,
                     int N, float invN) {
    __shared__ float2 s_v[MAXV][TPB];   // 32KB; row stride 2048B -> lane-invariant banks
    const int tid = threadIdx.x;
    float2* const col = &s_v[0][tid];   // row k at col[k*TPB]

    float loss = 0.0f;
    for (int i = blockIdx.x * TPB + tid; i < N; i += gridDim.x * TPB) {
        const float* P = pred + (size_t)i * 5;
        const float* T = target + (size_t)i * 5;
        float p_cx = P[0], p_cy = P[1], p_w = P[2], p_h = P[3], p_a = P[4];
        float t_cx = T[0], t_cy = T[1], t_w = T[2], t_h = T[3], t_a = T[4];

        float c1, s1, c2, s2;
        __sincosf(p_a, &s1, &c1);
        __sincosf(t_a, &s2, &c2);

        // ---- box1-local frame: box1 axis-aligned, box2 rotated by delta ----
        float hw = 0.5f * p_w, hh = 0.5f * p_h;
        float dxg = t_cx - p_cx, dyg = t_cy - p_cy;
        float rcx =  c1 * dxg + s1 * dyg;          // R1^T * (c2 - c1)
        float rcy =  c1 * dyg - s1 * dxg;
        float cd = c1 * c2 + s1 * s2;              // cos(a2 - a1)
        float sd = c1 * s2 - s1 * c2;              // sin(a2 - a1)

        float X2[4], Y2[4];
        box_corners(rcx, rcy, t_w, t_h, cd, sd, X2, Y2);

        // box1 corners (CW, reference order) in local frame
        const float X1a[4] = { hw, -hw, -hw,  hw };
        const float Y1a[4] = {-hh, -hh,  hh,  hh };

        // inclusion bounds (== reference p_ab/p_ad in (-tol, 1+tol))
        float bx1 = hw + BTOL * p_w, by1 = hh + BTOL * p_h;
        float bx2 = 0.5f * t_w + BTOL * t_w, by2 = 0.5f * t_h + BTOL * t_h;

        // ---- collect valid vertices (reference concatenation order) ----
        int m = 0;
        float sx = 0.0f, sy = 0.0f;

        // corners1 in box2: rotate into box2 frame, bound check
        #pragma unroll
        for (int k = 0; k < 4; k++) {
            float ux = X1a[k] - rcx, uy = Y1a[k] - rcy;
            float qx = cd * ux + sd * uy;
            float qy = cd * uy - sd * ux;
            if (fabsf(qx) < bx2 && fabsf(qy) < by2) {
                col[m * TPB] = make_float2(X1a[k], Y1a[k]);
                sx += X1a[k]; sy += Y1a[k]; m++;
            }
        }
        // corners2 in box1: direct bound check (box1 axis-aligned)
        #pragma unroll
        for (int k = 0; k < 4; k++) {
            if (fabsf(X2[k]) < bx1 && fabsf(Y2[k]) < by1) {
                col[m * TPB] = make_float2(X2[k], Y2[k]);
                sx += X2[k]; sy += Y2[k]; m++;
            }
        }
        // segment intersections, k1-major (matches reshape order).
        // Sign-factored tests: ex/ey have compile-time zero/sign, w,h > 0.
        //  original: den_t*num>0 && |den_t|<|num| && den_u*num<0 && |den_u|<|num|
        // k1=0: x1=hw, y1=-hh, ex=-p_w, ey=0  -> num=-p_w*fy, den_u=-p_w*ay
        #pragma unroll
        for (int k2 = 0; k2 < 4; k2++) {
            float fx = X2[(k2 + 1) & 3] - X2[k2], fy = Y2[(k2 + 1) & 3] - Y2[k2];
            float ax = hw - X2[k2], ay = -hh - Y2[k2];
            float den_t = fx * ay - fy * ax;
            bool ok = (ay * fy < 0.0f) && (fabsf(ay) < fabsf(fy)) &&
                      (den_t * fy < 0.0f) && (fabsf(den_t) < p_w * fabsf(fy));
            if (ok) {
                float num = -p_w * fy;
                float t = __fdividef(den_t, num + NEPS);
                float ix = fmaf(t, -p_w, hw);
                col[m * TPB] = make_float2(ix, -hh);
                sx += ix; sy += -hh; m++;
            }
        }
        // k1=1: x1=-hw, y1=-hh, ex=0, ey=p_h -> num=-p_h*fx, den_u=-p_h*ax
        #pragma unroll
        for (int k2 = 0; k2 < 4; k2++) {
            float fx = X2[(k2 + 1) & 3] - X2[k2], fy = Y2[(k2 + 1) & 3] - Y2[k2];
            float ax = -hw - X2[k2], ay = -hh - Y2[k2];
            float den_t = fx * ay - fy * ax;
            bool ok = (ax * fx < 0.0f) && (fabsf(ax) < fabsf(fx)) &&
                      (den_t * fx < 0.0f) && (fabsf(den_t) < p_h * fabsf(fx));
            if (ok) {
                float num = -p_h * fx;
                float t = __fdividef(den_t, num + NEPS);
                float iy = fmaf(t, p_h, -hh);
                col[m * TPB] = make_float2(-hw, iy);
                sx += -hw; sy += iy; m++;
            }
        }
        // k1=2: x1=-hw, y1=hh, ex=p_w, ey=0  -> num=p_w*fy, den_u=p_w*ay
        #pragma unroll
        for (int k2 = 0; k2 < 4; k2++) {
            float fx = X2[(k2 + 1) & 3] - X2[k2], fy = Y2[(k2 + 1) & 3] - Y2[k2];
            float ax = -hw - X2[k2], ay = hh - Y2[k2];
            float den_t = fx * ay - fy * ax;
            bool ok = (ay * fy < 0.0f) && (fabsf(ay) < fabsf(fy)) &&
                      (den_t * fy > 0.0f) && (fabsf(den_t) < p_w * fabsf(fy));
            if (ok) {
                float num = p_w * fy;
                float t = __fdividef(den_t, num + NEPS);
                float ix = fmaf(t, p_w, -hw);
                col[m * TPB] = make_float2(ix, hh);
                sx += ix; sy += hh; m++;
            }
        }
        // k1=3: x1=hw, y1=hh, ex=0, ey=-p_h -> num=p_h*fx, den_u=p_h*ax
        #pragma unroll
        for (int k2 = 0; k2 < 4; k2++) {
            float fx = X2[(k2 + 1) & 3] - X2[k2], fy = Y2[(k2 + 1) & 3] - Y2[k2];
            float ax = hw - X2[k2], ay = hh - Y2[k2];
            float den_t = fx * ay - fy * ax;
            bool ok = (ax * fx < 0.0f) && (fabsf(ax) < fabsf(fx)) &&
                      (den_t * fx > 0.0f) && (fabsf(den_t) < p_h * fabsf(fx));
            if (ok) {
                float num = p_h * fx;
                float t = __fdividef(den_t, num + NEPS);
                float iy = fmaf(t, -p_h, hh);
                col[m * TPB] = make_float2(hw, iy);
                sx += hw; sy += iy; m++;
            }
        }

        // ---- order by centroid angle, shoelace (area frame-invariant) ----
        float inter_area = 0.0f;
        if (m > 2 && m <= 8) {
            float imf = __fdividef(1.0f, (float)m);
            float ccx = sx * imf, ccy = sy * imf;

            unsigned int key[8];
            #pragma unroll
            for (int slot = 0; slot < 8; slot++) {
                unsigned int kk = 0xFFFFFFFFu;   // sentinel sorts last
                if (slot < m) {
                    float2 v = col[slot * TPB];
                    unsigned int u = ordered_bits(pseudo_angle(v.x - ccx, v.y - ccy));
                    kk = (u & 0xFFFFFFE0u) | (unsigned int)slot;
                }
                key[slot] = kk;
            }
            // Batcher odd-even merge sort, 8 elements, 19 comparators
            CE(0,1) CE(2,3) CE(4,5) CE(6,7)
            CE(0,2) CE(1,3) CE(4,6) CE(5,7)
            CE(1,2) CE(5,6)
            CE(0,4) CE(1,5) CE(2,6) CE(3,7)
            CE(2,4) CE(3,5)
            CE(1,2) CE(3,4) CE(5,6)

            float2 f0 = col[(int)(key[0] & 0x1Fu) * TPB];
            float px = f0.x, py = f0.y;
            float s = 0.0f;
            #pragma unroll
            for (int r = 1; r < 8; r++) {
                if (r < m) {
                    float2 v = col[(int)(key[r] & 0x1Fu) * TPB];
                    s = fmaf(px, v.y, s);
                    s = fmaf(-py, v.x, s);
                    px = v.x; py = v.y;
                }
            }
            s = fmaf(px, f0.y, s);
            s = fmaf(-py, f0.x, s);
            inter_area = fabsf(s) * 0.5f;
        } else if (m > 8) {
            // rare fallback (tolerance-degenerate)
            float imf = __fdividef(1.0f, (float)m);
            float ccx = sx * imf, ccy = sy * imf;

            unsigned int key[MAXV];
            for (int k = 0; k < m; k++) {
                float2 v = col[k * TPB];
                unsigned int u = ordered_bits(pseudo_angle(v.x - ccx, v.y - ccy));
                key[k] = (u & 0xFFFFFFE0u) | (unsigned int)k;
            }
            for (int k = 1; k < m; k++) {
                unsigned int kv = key[k];
                int j = k - 1;
                while (j >= 0 && key[j] > kv) { key[j + 1] = key[j]; j--; }
                key[j + 1] = kv;
            }
            float2 f0 = col[(int)(key[0] & 0x1Fu) * TPB];
            float px = f0.x, py = f0.y;
            float s = 0.0f;
            for (int k = 1; k < m; k++) {
                float2 v = col[(int)(key[k] & 0x1Fu) * TPB];
                s = fmaf(px, v.y, s);
                s = fmaf(-py, v.x, s);
                px = v.x; py = v.y;
            }
            s = fmaf(px, f0.y, s);
            s = fmaf(-py, f0.x, s);
            inter_area = fabsf(s) * 0.5f;
        }

        float area1 = p_w * p_h;
        float area2 = t_w * t_h;
        float iou = __fdividef(inter_area, area1 + area2 - inter_area);
        iou = fminf(fmaxf(iou, 0.0f), 1.0f);

        // horizontal enclosing box (global frame)
        float ac1 = fabsf(c1), as1 = fabsf(s1);
        float ac2 = fabsf(c2), as2 = fabsf(s2);
        float dw1 = (p_w * ac1 + p_h * as1) * 0.5f;
        float dh1 = (p_w * as1 + p_h * ac1) * 0.5f;
        float dw2 = (t_w * ac2 + t_h * as2) * 0.5f;
        float dh2 = (t_w * as2 + t_h * ac2) * 0.5f;
        float en_w = fmaxf(fmaxf(p_cx + dw1, t_cx + dw2) - fminf(p_cx - dw1, t_cx - dw2), 0.0f);
        float en_h = fmaxf(fmaxf(p_cy + dh1, t_cy + dh2) - fminf(p_cy - dh1, t_cy - dh2), 0.0f);
        float c2v = en_w * en_w + en_h * en_h + MEPS;

        float rho2 = dxg * dxg + dyg * dyg;

        const float factor = 0.40528473456935108577f;  // 4/pi^2
        float dv = fast_atan_pos(__fdividef(t_w, t_h + MEPS)) -
                   fast_atan_pos(__fdividef(p_w, p_h + MEPS));
        float v = factor * dv * dv;
        float alpha = (iou > 0.5f) ? __fdividef(v, 1.0f - iou + v + MEPS) : 0.0f;

        float ciou = iou - (fminf(fmaxf(__fdividef(rho2, c2v), 0.0f), 1.0f) + alpha * v);
        loss += (1.0f - ciou) * weight[i];
    }

    // ---- deterministic fixed-order reduction ----
    #pragma unroll
    for (int o = 16; o > 0; o >>= 1)
        loss += __shfl_down_sync(0xffffffffu, loss, o);
    __shared__ float sm[TPB / 32];
    __shared__ bool isLast;
    if ((tid & 31) == 0) sm[tid >> 5] = loss;
    __syncthreads();
    if (tid < 32) {
        float vsum = (tid < TPB / 32) ? sm[tid] : 0.0f;
        #pragma unroll
        for (int o = TPB / 64; o > 0; o >>= 1)
            vsum += __shfl_down_sync(0xffffffffu, vsum, o);
        if (tid == 0) {
            g_partials[blockIdx.x] = vsum;
            __threadfence();
            int prev = atomicAdd(&g_count, 1);
            isLast = (prev == (int)gridDim.x - 1);
        }
    }
    __syncthreads();
    if (isLast) {
        int nb = gridDim.x;
        float s = 0.0f;
        for (int k = tid; k < nb; k += TPB) s += g_partials[k];
        #pragma unroll
        for (int o = 16; o > 0; o >>= 1)
            s += __shfl_down_sync(0xffffffffu, s, o);
        if ((tid & 31) == 0) sm[tid >> 5] = s;
        __syncthreads();
        if (tid < 32) {
            float vs = (tid < TPB / 32) ? sm[tid] : 0.0f;
            #pragma unroll
            for (int o = TPB / 64; o > 0; o >>= 1)
                vs += __shfl_down_sync(0xffffffffu, vs, o);
            if (tid == 0) {
                out[0] = vs * invN;
                g_count = 0;   // reset for next graph replay
            }
        }
    }
}

extern "C" void kernel_launch(void* const* d_in, const int* in_sizes, int n_in,
                              void* d_out, int out_size) {
    const float* pred   = (const float*)d_in[0];
    const float* target = (const float*)d_in[1];
    const float* weight = (const float*)d_in[2];
    int N = in_sizes[2];  // weight has N elements

    int nb = (N + TPB - 1) / TPB;
    if (nb > RED_MAX) nb = RED_MAX;
    if (nb < 1) nb = 1;

    obb_ciou_kernel<<<nb, TPB>>>(pred, target, weight, (float*)d_out,
                                 N, 1.0f / (float)N);
}